// round 7
// baseline (speedup 1.0000x reference)
#include <cuda_runtime.h>
#include <cuda_fp16.h>
#include <cstdint>

#define NROW 8192
#define FDIM 512
#define LDBM 520          // B cols: 512 feats + 8 den

// ------------------------- scratch -------------------------
__device__ __half   g_X16[(size_t)NROW * FDIM];
__device__ __half   g_Wt [(size_t)FDIM * FDIM];   // Wt[f][c], c=h*64+o
__device__ float    g_WX [(size_t)NROW * FDIM];
__device__ float    g_s2 [8 * NROW];
__device__ unsigned g_mxi[8];
__device__ __half   g_B  [(size_t)NROW * LDBM];   // B[j][c]: w*WX (c<512), w (512..519)

__device__ __forceinline__ unsigned enc_f(float f) {
    unsigned u = __float_as_uint(f);
    return (u & 0x80000000u) ? ~u : (u | 0x80000000u);
}
__device__ __forceinline__ float dec_f(unsigned e) {
    unsigned u = (e & 0x80000000u) ? (e ^ 0x80000000u) : ~e;
    return __uint_as_float(u);
}

// ------------------------- templated mma.sync GEMM -------------------------
// C[m0+128, n0+BN] = A[M,KLEN] @ B[k][n].
// CONV: A fp32 -> LDG to regs -> fp16 regs -> 2-slot smem ring (no A32 staging).
// DEN:  8 extra B cols (512..519) accumulated by wn==0 warps; epilogue writes
//       relu(acc/den) straight to C (stride 512).
// S2:   epilogue also accumulates s2[h,row] = dot(C_row_tile, a2) via atomicAdd.
template<int KLEN, int LDBg, int BN, bool CONV, bool DEN, bool S2>
__global__ __launch_bounds__(256, 1)
void k_mm(const void* Ag_, const __half* __restrict__ Bg, float* __restrict__ Cg,
          const float* __restrict__ attn)
{
    constexpr int NKT    = KLEN / 32;
    constexpr int BSTR   = (BN == 128) ? 136 : 280;   // halves; conflict-free ldmatrix
    constexpr int NI     = BN / 32;
    constexpr int CPR    = BN / 8 + (DEN ? 1 : 0);    // 16B chunks per B row
    constexpr int A16_SZ = 128 * 40 * 2;              // 10240
    constexpr int B_SZ   = 32 * BSTR * 2;
    constexpr int NA16   = CONV ? 2 : 4;
    constexpr int OFF_B  = NA16 * A16_SZ;
    constexpr int OFF_DEN = OFF_B + 4 * B_SZ;

    extern __shared__ char smem[];
    const uint32_t sbase = (uint32_t)__cvta_generic_to_shared(smem);

    const int tid = threadIdx.x;
    const int wid = tid >> 5, lane = tid & 31;
    const int wm = wid & 1, wn = wid >> 1;
    const int lr = lane & 15, lc = (lane >> 4) * 8;
    const int l4 = lane & 3,  lg = lane >> 2;
    const int m0 = blockIdx.y * 128, n0 = blockIdx.x * BN;

    const float*  A32g = (const float*)Ag_;
    const __half* A16g = (const __half*)Ag_;

    float acc[4][NI][4];
    #pragma unroll
    for (int a = 0; a < 4; a++)
        #pragma unroll
        for (int b = 0; b < NI; b++)
            #pragma unroll
            for (int c = 0; c < 4; c++) acc[a][b][c] = 0.f;
    float accD[4][4];
    if (DEN) {
        #pragma unroll
        for (int a = 0; a < 4; a++)
            #pragma unroll
            for (int c = 0; c < 4; c++) accD[a][c] = 0.f;
    }

    // ---- A fp32 -> registers (CONV path) ----
    float4 rb[2][4];
    const float* gA = CONV
        ? A32g + (size_t)(m0 + (tid >> 1)) * KLEN + (tid & 1) * 16 : nullptr;
    auto ldgA = [&](int kt, float4* r) {
        const float4* p = reinterpret_cast<const float4*>(gA + (size_t)kt * 32);
        r[0] = __ldg(p); r[1] = __ldg(p + 1); r[2] = __ldg(p + 2); r[3] = __ldg(p + 3);
    };
    auto cstore = [&](int kt, const float4* v) {       // regs -> A16[kt&1]
        union { uint4 u; __half2 h[4]; } p0, p1;
        p0.h[0] = __floats2half2_rn(v[0].x, v[0].y);
        p0.h[1] = __floats2half2_rn(v[0].z, v[0].w);
        p0.h[2] = __floats2half2_rn(v[1].x, v[1].y);
        p0.h[3] = __floats2half2_rn(v[1].z, v[1].w);
        p1.h[0] = __floats2half2_rn(v[2].x, v[2].y);
        p1.h[1] = __floats2half2_rn(v[2].z, v[2].w);
        p1.h[2] = __floats2half2_rn(v[3].x, v[3].y);
        p1.h[3] = __floats2half2_rn(v[3].z, v[3].w);
        __half* d = (__half*)(smem + (kt & 1) * A16_SZ) + (tid >> 1) * 40 + (tid & 1) * 16;
        ((uint4*)d)[0] = p0.u;
        ((uint4*)d)[1] = p1.u;
    };

    auto load_stage = [&](int kt) {                    // B (and A16 when !CONV)
        if (!CONV) {
            uint32_t sa = sbase + (kt & 3) * A16_SZ;
            const __half* g0 = A16g + (size_t)m0 * KLEN + (size_t)kt * 32;
            #pragma unroll
            for (int i = 0; i < 2; i++) {
                int ch = i * 256 + tid;
                int r = ch >> 2, c8 = ch & 3;
                asm volatile("cp.async.cg.shared.global [%0], [%1], 16;"
                             :: "r"(sa + r * 80 + c8 * 16),
                                "l"(g0 + (size_t)r * KLEN + c8 * 8));
            }
        }
        uint32_t sb = sbase + OFF_B + (kt & 3) * B_SZ;
        const __half* gb = Bg + (size_t)kt * 32 * LDBg;
        #pragma unroll
        for (int ch = tid; ch < 32 * CPR; ch += 256) {
            int r = ch / CPR, cc = ch % CPR;
            int gcol = (cc < BN / 8) ? (n0 + cc * 8) : 512;
            asm volatile("cp.async.cg.shared.global [%0], [%1], 16;"
                         :: "r"(sb + r * (BSTR * 2) + cc * 16),
                            "l"(gb + (size_t)r * LDBg + gcol));
        }
    };

    auto compute = [&](int kt) {
        const uint32_t a16b = sbase + (CONV ? (kt & 1) : (kt & 3)) * A16_SZ;
        const uint32_t bb   = sbase + OFF_B + (kt & 3) * B_SZ;
        #pragma unroll
        for (int ks = 0; ks < 2; ks++) {
            uint32_t af[4][4], bf[NI][2], dn[2];
            #pragma unroll
            for (int mi = 0; mi < 4; mi++) {
                uint32_t ad = a16b + ((wm * 64 + mi * 16 + lr) * 40 + ks * 16 + lc) * 2;
                asm volatile("ldmatrix.sync.aligned.m8n8.x4.shared.b16 {%0,%1,%2,%3}, [%4];"
                             : "=r"(af[mi][0]), "=r"(af[mi][1]),
                               "=r"(af[mi][2]), "=r"(af[mi][3]) : "r"(ad));
            }
            #pragma unroll
            for (int nj = 0; nj < NI / 2; nj++) {
                uint32_t bd_ = bb + ((ks * 16 + lr) * BSTR + wn * (BN / 4) + nj * 16 + lc) * 2;
                asm volatile("ldmatrix.sync.aligned.m8n8.x4.trans.shared.b16 {%0,%1,%2,%3}, [%4];"
                             : "=r"(bf[nj * 2][0]), "=r"(bf[nj * 2][1]),
                               "=r"(bf[nj * 2 + 1][0]), "=r"(bf[nj * 2 + 1][1]) : "r"(bd_));
            }
            if (DEN && wn == 0) {
                uint32_t dd = bb + ((ks * 16 + lr) * BSTR + BN) * 2;
                asm volatile("ldmatrix.sync.aligned.m8n8.x2.trans.shared.b16 {%0,%1}, [%2];"
                             : "=r"(dn[0]), "=r"(dn[1]) : "r"(dd));
            }
            #pragma unroll
            for (int mi = 0; mi < 4; mi++) {
                #pragma unroll
                for (int ni = 0; ni < NI; ni++)
                    asm volatile(
                        "mma.sync.aligned.m16n8k16.row.col.f32.f16.f16.f32 "
                        "{%0,%1,%2,%3}, {%4,%5,%6,%7}, {%8,%9}, {%0,%1,%2,%3};"
                        : "+f"(acc[mi][ni][0]), "+f"(acc[mi][ni][1]),
                          "+f"(acc[mi][ni][2]), "+f"(acc[mi][ni][3])
                        : "r"(af[mi][0]), "r"(af[mi][1]), "r"(af[mi][2]), "r"(af[mi][3]),
                          "r"(bf[ni][0]), "r"(bf[ni][1]));
                if (DEN && wn == 0)
                    asm volatile(
                        "mma.sync.aligned.m16n8k16.row.col.f32.f16.f16.f32 "
                        "{%0,%1,%2,%3}, {%4,%5,%6,%7}, {%8,%9}, {%0,%1,%2,%3};"
                        : "+f"(accD[mi][0]), "+f"(accD[mi][1]),
                          "+f"(accD[mi][2]), "+f"(accD[mi][3])
                        : "r"(af[mi][0]), "r"(af[mi][1]), "r"(af[mi][2]), "r"(af[mi][3]),
                          "r"(dn[0]), "r"(dn[1]));
            }
        }
    };

    // ---- preamble ----
    if (CONV) { ldgA(0, rb[0]); ldgA(1, rb[1]); }
    load_stage(0); asm volatile("cp.async.commit_group;");
    load_stage(1); asm volatile("cp.async.commit_group;");
    load_stage(2); asm volatile("cp.async.commit_group;");
    if (CONV) cstore(0, rb[0]);
    asm volatile("cp.async.wait_group 2;");
    __syncthreads();

    #pragma unroll 1
    for (int kt = 0; kt < NKT; kt++) {
        if (CONV && kt + 2 < NKT) ldgA(kt + 2, rb[kt & 1]);
        compute(kt);
        if (CONV && kt + 1 < NKT) cstore(kt + 1, rb[(kt + 1) & 1]);
        if (kt + 3 < NKT) { load_stage(kt + 3); asm volatile("cp.async.commit_group;"); }
        asm volatile("cp.async.wait_group 2;");
        __syncthreads();
    }

    // ---- epilogue ----
    float* ds = (float*)(smem + OFF_DEN);
    if (DEN) {
        if (wn == 0) {
            #pragma unroll
            for (int mi = 0; mi < 4; mi++) {
                int r = wm * 64 + mi * 16 + lg;
                ds[r * 8 + l4 * 2]           = 1.f / accD[mi][0];
                ds[r * 8 + l4 * 2 + 1]       = 1.f / accD[mi][1];
                ds[(r + 8) * 8 + l4 * 2]     = 1.f / accD[mi][2];
                ds[(r + 8) * 8 + l4 * 2 + 1] = 1.f / accD[mi][3];
            }
        }
        __syncthreads();
    }
    #pragma unroll
    for (int mi = 0; mi < 4; mi++) {
        int rl = wm * 64 + mi * 16 + lg;
        int rg = m0 + rl;
        #pragma unroll
        for (int ni = 0; ni < NI; ni++) {
            int c = n0 + wn * (BN / 4) + ni * 8 + l4 * 2;
            if (DEN) {
                int h = c >> 6;
                float d0 = ds[rl * 8 + h], d1 = ds[(rl + 8) * 8 + h];
                *reinterpret_cast<float2*>(&Cg[(size_t)rg * 512 + c]) =
                    make_float2(fmaxf(acc[mi][ni][0] * d0, 0.f),
                                fmaxf(acc[mi][ni][1] * d0, 0.f));
                *reinterpret_cast<float2*>(&Cg[(size_t)(rg + 8) * 512 + c]) =
                    make_float2(fmaxf(acc[mi][ni][2] * d1, 0.f),
                                fmaxf(acc[mi][ni][3] * d1, 0.f));
            } else {
                *reinterpret_cast<float2*>(&Cg[(size_t)rg * 512 + c]) =
                    make_float2(acc[mi][ni][0], acc[mi][ni][1]);
                *reinterpret_cast<float2*>(&Cg[(size_t)(rg + 8) * 512 + c]) =
                    make_float2(acc[mi][ni][2], acc[mi][ni][3]);
            }
        }
    }
    if (S2) {                                          // fused s2 partial dot
        const int hh = (n0 + wn * 32) >> 6;
        const float* a2 = attn + hh * 128 + 64;
        float a2v[NI][2];
        #pragma unroll
        for (int ni = 0; ni < NI; ni++) {
            int c = (wn * 32 + ni * 8 + l4 * 2) & 63;
            a2v[ni][0] = __ldg(a2 + c);
            a2v[ni][1] = __ldg(a2 + c + 1);
        }
        #pragma unroll
        for (int mi = 0; mi < 4; mi++) {
            float p0 = 0.f, p1 = 0.f;
            #pragma unroll
            for (int ni = 0; ni < NI; ni++) {
                p0 += acc[mi][ni][0] * a2v[ni][0] + acc[mi][ni][1] * a2v[ni][1];
                p1 += acc[mi][ni][2] * a2v[ni][0] + acc[mi][ni][3] * a2v[ni][1];
            }
            p0 += __shfl_xor_sync(0xFFFFFFFFu, p0, 1);
            p0 += __shfl_xor_sync(0xFFFFFFFFu, p0, 2);
            p1 += __shfl_xor_sync(0xFFFFFFFFu, p1, 1);
            p1 += __shfl_xor_sync(0xFFFFFFFFu, p1, 2);
            if (l4 == 0) {
                int r = m0 + wm * 64 + mi * 16 + lg;
                atomicAdd(&g_s2[hh * NROW + r], p0);
                atomicAdd(&g_s2[hh * NROW + r + 8], p1);
            }
        }
    }
}

// ------------------------- prep / small kernels -------------------------
__global__ void k_prep(const float* __restrict__ X, const float* __restrict__ kern) {
    int b = blockIdx.x;
    if (b < 4096) {                                    // X -> fp16
        size_t i = (size_t)b * 256 + threadIdx.x;
        float4 v = reinterpret_cast<const float4*>(X)[i];
        __half2* d = reinterpret_cast<__half2*>(g_X16);
        d[2 * i]     = __floats2half2_rn(v.x, v.y);
        d[2 * i + 1] = __floats2half2_rn(v.z, v.w);
    } else if (b < 5120) {                             // kernels -> Wt[f][c]
        size_t i = (size_t)(b - 4096) * 256 + threadIdx.x;
        int f = (int)(i >> 9), c = (int)(i & 511);
        g_Wt[i] = __float2half_rn(kern[((size_t)(c >> 6) * 512 + f) * 64 + (c & 63)]);
    } else if (b < 5376) {                             // zero s2 (graph-replay safe)
        g_s2[(b - 5120) * 256 + threadIdx.x] = 0.f;
    } else {
        if (threadIdx.x < 8) g_mxi[threadIdx.x] = 0u;
    }
}

__global__ void k_max64() {                            // grid 64, block 256
    __shared__ float sm[256];
    int h = blockIdx.x >> 3, seg = blockIdx.x & 7;
    float m = -1e30f;
    for (int i = seg * 1024 + threadIdx.x; i < (seg + 1) * 1024; i += 256)
        m = fmaxf(m, g_s2[h * NROW + i]);
    sm[threadIdx.x] = m;
    __syncthreads();
    for (int s = 128; s > 0; s >>= 1) {
        if (threadIdx.x < s) sm[threadIdx.x] = fmaxf(sm[threadIdx.x], sm[threadIdx.x + s]);
        __syncthreads();
    }
    if (threadIdx.x == 0) atomicMax(&g_mxi[h], enc_f(sm[0]));
}

__global__ void k_buildB() {                           // grid 8192, block 544
    int n = blockIdx.x;
    int c = threadIdx.x;
    if (c >= LDBM) return;
    int h = (c < 512) ? (c >> 6) : (c - 512);
    float w = __expf(g_s2[h * NROW + n] - dec_f(g_mxi[h]));
    float v = (c < 512) ? w * g_WX[(size_t)n * FDIM + c] : w;
    g_B[(size_t)n * LDBM + c] = __float2half_rn(v);
}

// ------------------------- launcher -------------------------
extern "C" void kernel_launch(void* const* d_in, const int* in_sizes, int n_in,
                              void* d_out, int out_size)
{
    const float* X    = (const float*)d_in[0];
    const float* A    = (const float*)d_in[1];
    const float* kern = (const float*)d_in[2];
    const float* attn = (const float*)d_in[3];
    float* out = (float*)d_out;

    void *pX16, *pWt, *pWX, *pB;
    cudaGetSymbolAddress(&pX16, g_X16);
    cudaGetSymbolAddress(&pWt,  g_Wt);
    cudaGetSymbolAddress(&pWX,  g_WX);
    cudaGetSymbolAddress(&pB,   g_B);

    constexpr int SM_WX   = 4 * 10240 + 4 * (32 * 136 * 2);                 // 75776
    constexpr int SM_MAIN = 2 * 10240 + 4 * (32 * 280 * 2) + 4096;          // 96256
    cudaFuncSetAttribute(k_mm<FDIM, FDIM, 128, false, false, true>,
                         cudaFuncAttributeMaxDynamicSharedMemorySize, SM_WX);
    cudaFuncSetAttribute(k_mm<NROW, LDBM, 256, true, true, false>,
                         cudaFuncAttributeMaxDynamicSharedMemorySize, SM_MAIN);

    // 1: fp16 operands + zero s2/max
    k_prep<<<5377, 256>>>(X, kern);
    // 2: WX = X16 @ Wt, with fused s2 accumulation
    k_mm<FDIM, FDIM, 128, false, false, true><<<dim3(4, 64), 256, SM_WX>>>(
        pX16, (const __half*)pWt, (float*)pWX, attn);
    // 3-4: per-head max, B build (feats + den cols)
    k_max64<<<64, 256>>>();
    k_buildB<<<NROW, 544>>>();
    // 5: main fused GEMM (reg-side A conversion, den cols, div+relu) -> out
    k_mm<NROW, LDBM, 256, true, true, false><<<dim3(2, 64), 256, SM_MAIN>>>(
        A, (const __half*)pB, out, nullptr);
}

// round 8
// speedup vs baseline: 1.3525x; 1.3525x over previous
#include <cuda_runtime.h>
#include <cuda_fp16.h>
#include <cstdint>

#define NROW 8192
#define FDIM 512
#define LDBM 520          // B cols: 512 feats + 8 den

#define SWZ(x) ((x) ^ (((x) >> 3) & 0x70))

// ------------------------- scratch -------------------------
__device__ __half   g_X16[(size_t)NROW * FDIM];
__device__ __half   g_Wt [(size_t)FDIM * FDIM];   // Wt[f][c], c=h*64+o
__device__ float    g_WX [(size_t)NROW * FDIM];
__device__ float    g_s2 [8 * NROW];
__device__ unsigned g_mxi[8];
__device__ __half   g_B  [(size_t)NROW * LDBM];   // B[j][c]: w*WX (c<512), w (512..519)

__device__ __forceinline__ unsigned enc_f(float f) {
    unsigned u = __float_as_uint(f);
    return (u & 0x80000000u) ? ~u : (u | 0x80000000u);
}
__device__ __forceinline__ float dec_f(unsigned e) {
    unsigned u = (e & 0x80000000u) ? (e ^ 0x80000000u) : ~e;
    return __uint_as_float(u);
}

// ------------------------- templated mma.sync GEMM -------------------------
// C[m0+128, n0+BN] = A[M,KLEN] @ B[k][n].
// CONV: A fp32 staged via swizzled smem ring, converted to a 2-slot fp16 ring;
//       convert(kt+1) is issued BEFORE compute(kt) so it overlaps tensor drain.
// DEN:  8 extra B cols (512..519) accumulated by wn==0 warps; epilogue writes
//       relu(acc/den) straight to C (stride 512).
// S2:   epilogue accumulates s2[h,row] = dot(C_row_tile, a2) via atomicAdd.
template<int KLEN, int LDBg, int BN, bool CONV, bool DEN, bool S2>
__global__ __launch_bounds__(256, 1)
void k_mm(const void* Ag_, const __half* __restrict__ Bg, float* __restrict__ Cg,
          const float* __restrict__ attn)
{
    constexpr int NKT    = KLEN / 32;
    constexpr int BSTR   = (BN == 128) ? 136 : 280;   // halves; conflict-free ldmatrix
    constexpr int NI     = BN / 32;
    constexpr int CPR    = BN / 8 + (DEN ? 1 : 0);    // 16B chunks per B row
    constexpr int A32_SZ = 128 * 32 * 4;              // 16384
    constexpr int A16_SZ = 128 * 40 * 2;              // 10240
    constexpr int B_SZ   = 32 * BSTR * 2;
    constexpr int OFF_A16 = CONV ? 4 * A32_SZ : 0;
    constexpr int OFF_B   = OFF_A16 + (CONV ? 2 : 4) * A16_SZ;
    constexpr int OFF_DEN = OFF_B + 4 * B_SZ;

    extern __shared__ char smem[];
    const uint32_t sbase = (uint32_t)__cvta_generic_to_shared(smem);

    const int tid = threadIdx.x;
    const int wid = tid >> 5, lane = tid & 31;
    const int wm = wid & 1, wn = wid >> 1;
    const int lr = lane & 15, lc = (lane >> 4) * 8;
    const int l4 = lane & 3,  lg = lane >> 2;
    const int m0 = blockIdx.y * 128, n0 = blockIdx.x * BN;

    const float*  A32g = (const float*)Ag_;
    const __half* A16g = (const __half*)Ag_;

    float acc[4][NI][4];
    #pragma unroll
    for (int a = 0; a < 4; a++)
        #pragma unroll
        for (int b = 0; b < NI; b++)
            #pragma unroll
            for (int c = 0; c < 4; c++) acc[a][b][c] = 0.f;
    float accD[4][4];
    if (DEN) {
        #pragma unroll
        for (int a = 0; a < 4; a++)
            #pragma unroll
            for (int c = 0; c < 4; c++) accD[a][c] = 0.f;
    }

    auto load_stage = [&](int kt) {
        if (CONV) {
            uint32_t sa = sbase + (kt & 3) * A32_SZ;
            const float* g0 = A32g + (size_t)m0 * KLEN + (size_t)kt * 32;
            #pragma unroll
            for (int i = 0; i < 4; i++) {              // 1024 16B chunks (swizzled)
                int ch = i * 256 + tid;
                int r = ch >> 3, c4 = ch & 7;
                asm volatile("cp.async.cg.shared.global [%0], [%1], 16;"
                             :: "r"(sa + SWZ(r * 128 + c4 * 16)),
                                "l"(g0 + (size_t)r * KLEN + c4 * 4));
            }
        } else {
            uint32_t sa = sbase + OFF_A16 + (kt & 3) * A16_SZ;
            const __half* g0 = A16g + (size_t)m0 * KLEN + (size_t)kt * 32;
            #pragma unroll
            for (int i = 0; i < 2; i++) {
                int ch = i * 256 + tid;
                int r = ch >> 2, c8 = ch & 3;
                asm volatile("cp.async.cg.shared.global [%0], [%1], 16;"
                             :: "r"(sa + r * 80 + c8 * 16),
                                "l"(g0 + (size_t)r * KLEN + c8 * 8));
            }
        }
        uint32_t sb = sbase + OFF_B + (kt & 3) * B_SZ;
        const __half* gb = Bg + (size_t)kt * 32 * LDBg;
        #pragma unroll
        for (int ch = tid; ch < 32 * CPR; ch += 256) {
            int r = ch / CPR, cc = ch % CPR;
            int gcol = (cc < BN / 8) ? (n0 + cc * 8) : 512;
            asm volatile("cp.async.cg.shared.global [%0], [%1], 16;"
                         :: "r"(sb + r * (BSTR * 2) + cc * 16),
                            "l"(gb + (size_t)r * LDBg + gcol));
        }
    };

    auto convert = [&](int kt) {                       // A32[kt&3] -> A16[kt&1]
        const char* s32 = smem + (kt & 3) * A32_SZ;
        const int row = tid >> 1, half = tid & 1;
        const uint32_t rb = row * 128 + half * 64;
        float4 v[4];
        #pragma unroll
        for (int j = 0; j < 4; j++)
            v[j] = *reinterpret_cast<const float4*>(s32 + SWZ(rb + j * 16));
        union { uint4 u; __half2 h[4]; } p0, p1;
        p0.h[0] = __floats2half2_rn(v[0].x, v[0].y);
        p0.h[1] = __floats2half2_rn(v[0].z, v[0].w);
        p0.h[2] = __floats2half2_rn(v[1].x, v[1].y);
        p0.h[3] = __floats2half2_rn(v[1].z, v[1].w);
        p1.h[0] = __floats2half2_rn(v[2].x, v[2].y);
        p1.h[1] = __floats2half2_rn(v[2].z, v[2].w);
        p1.h[2] = __floats2half2_rn(v[3].x, v[3].y);
        p1.h[3] = __floats2half2_rn(v[3].z, v[3].w);
        __half* d = (__half*)(smem + OFF_A16 + (kt & 1) * A16_SZ) + row * 40 + half * 16;
        ((uint4*)d)[0] = p0.u;
        ((uint4*)d)[1] = p1.u;
    };

    auto compute = [&](int kt) {
        const uint32_t a16b = sbase + OFF_A16 + (CONV ? (kt & 1) : (kt & 3)) * A16_SZ;
        const uint32_t bb   = sbase + OFF_B + (kt & 3) * B_SZ;
        #pragma unroll
        for (int ks = 0; ks < 2; ks++) {
            uint32_t af[4][4], bf[NI][2], dn[2];
            #pragma unroll
            for (int mi = 0; mi < 4; mi++) {
                uint32_t ad = a16b + ((wm * 64 + mi * 16 + lr) * 40 + ks * 16 + lc) * 2;
                asm volatile("ldmatrix.sync.aligned.m8n8.x4.shared.b16 {%0,%1,%2,%3}, [%4];"
                             : "=r"(af[mi][0]), "=r"(af[mi][1]),
                               "=r"(af[mi][2]), "=r"(af[mi][3]) : "r"(ad));
            }
            #pragma unroll
            for (int nj = 0; nj < NI / 2; nj++) {
                uint32_t bd_ = bb + ((ks * 16 + lr) * BSTR + wn * (BN / 4) + nj * 16 + lc) * 2;
                asm volatile("ldmatrix.sync.aligned.m8n8.x4.trans.shared.b16 {%0,%1,%2,%3}, [%4];"
                             : "=r"(bf[nj * 2][0]), "=r"(bf[nj * 2][1]),
                               "=r"(bf[nj * 2 + 1][0]), "=r"(bf[nj * 2 + 1][1]) : "r"(bd_));
            }
            if (DEN && wn == 0) {
                uint32_t dd = bb + ((ks * 16 + lr) * BSTR + BN) * 2;
                asm volatile("ldmatrix.sync.aligned.m8n8.x2.trans.shared.b16 {%0,%1}, [%2];"
                             : "=r"(dn[0]), "=r"(dn[1]) : "r"(dd));
            }
            #pragma unroll
            for (int mi = 0; mi < 4; mi++) {
                #pragma unroll
                for (int ni = 0; ni < NI; ni++)
                    asm volatile(
                        "mma.sync.aligned.m16n8k16.row.col.f32.f16.f16.f32 "
                        "{%0,%1,%2,%3}, {%4,%5,%6,%7}, {%8,%9}, {%0,%1,%2,%3};"
                        : "+f"(acc[mi][ni][0]), "+f"(acc[mi][ni][1]),
                          "+f"(acc[mi][ni][2]), "+f"(acc[mi][ni][3])
                        : "r"(af[mi][0]), "r"(af[mi][1]), "r"(af[mi][2]), "r"(af[mi][3]),
                          "r"(bf[ni][0]), "r"(bf[ni][1]));
                if (DEN && wn == 0)
                    asm volatile(
                        "mma.sync.aligned.m16n8k16.row.col.f32.f16.f16.f32 "
                        "{%0,%1,%2,%3}, {%4,%5,%6,%7}, {%8,%9}, {%0,%1,%2,%3};"
                        : "+f"(accD[mi][0]), "+f"(accD[mi][1]),
                          "+f"(accD[mi][2]), "+f"(accD[mi][3])
                        : "r"(af[mi][0]), "r"(af[mi][1]), "r"(af[mi][2]), "r"(af[mi][3]),
                          "r"(dn[0]), "r"(dn[1]));
            }
        }
    };

    // ---- preamble ----
    load_stage(0); asm volatile("cp.async.commit_group;");
    load_stage(1); asm volatile("cp.async.commit_group;");
    load_stage(2); asm volatile("cp.async.commit_group;");
    asm volatile("cp.async.wait_group 1;");            // stages 0,1 resident
    __syncthreads();
    if (CONV) { convert(0); __syncthreads(); }

    #pragma unroll 1
    for (int kt = 0; kt < NKT; kt++) {
        if (CONV && kt + 1 < NKT) convert(kt + 1);     // overlaps prev tensor drain
        compute(kt);
        if (kt + 3 < NKT) { load_stage(kt + 3); asm volatile("cp.async.commit_group;"); }
        if (CONV) asm volatile("cp.async.wait_group 1;");  // stage kt+2 resident
        else      asm volatile("cp.async.wait_group 2;");
        __syncthreads();
    }

    // ---- epilogue ----
    float* ds = (float*)(smem + OFF_DEN);
    if (DEN) {
        if (wn == 0) {
            #pragma unroll
            for (int mi = 0; mi < 4; mi++) {
                int r = wm * 64 + mi * 16 + lg;
                ds[r * 8 + l4 * 2]           = 1.f / accD[mi][0];
                ds[r * 8 + l4 * 2 + 1]       = 1.f / accD[mi][1];
                ds[(r + 8) * 8 + l4 * 2]     = 1.f / accD[mi][2];
                ds[(r + 8) * 8 + l4 * 2 + 1] = 1.f / accD[mi][3];
            }
        }
        __syncthreads();
    }
    #pragma unroll
    for (int mi = 0; mi < 4; mi++) {
        int rl = wm * 64 + mi * 16 + lg;
        int rg = m0 + rl;
        #pragma unroll
        for (int ni = 0; ni < NI; ni++) {
            int c = n0 + wn * (BN / 4) + ni * 8 + l4 * 2;
            if (DEN) {
                int h = c >> 6;
                float d0 = ds[rl * 8 + h], d1 = ds[(rl + 8) * 8 + h];
                *reinterpret_cast<float2*>(&Cg[(size_t)rg * 512 + c]) =
                    make_float2(fmaxf(acc[mi][ni][0] * d0, 0.f),
                                fmaxf(acc[mi][ni][1] * d0, 0.f));
                *reinterpret_cast<float2*>(&Cg[(size_t)(rg + 8) * 512 + c]) =
                    make_float2(fmaxf(acc[mi][ni][2] * d1, 0.f),
                                fmaxf(acc[mi][ni][3] * d1, 0.f));
            } else {
                *reinterpret_cast<float2*>(&Cg[(size_t)rg * 512 + c]) =
                    make_float2(acc[mi][ni][0], acc[mi][ni][1]);
                *reinterpret_cast<float2*>(&Cg[(size_t)(rg + 8) * 512 + c]) =
                    make_float2(acc[mi][ni][2], acc[mi][ni][3]);
            }
        }
    }
    if (S2) {                                          // fused s2 partial dot
        const int hh = (n0 + wn * 32) >> 6;
        const float* a2 = attn + hh * 128 + 64;
        float a2v[NI][2];
        #pragma unroll
        for (int ni = 0; ni < NI; ni++) {
            int c = (wn * 32 + ni * 8 + l4 * 2) & 63;
            a2v[ni][0] = __ldg(a2 + c);
            a2v[ni][1] = __ldg(a2 + c + 1);
        }
        #pragma unroll
        for (int mi = 0; mi < 4; mi++) {
            float p0 = 0.f, p1 = 0.f;
            #pragma unroll
            for (int ni = 0; ni < NI; ni++) {
                p0 += acc[mi][ni][0] * a2v[ni][0] + acc[mi][ni][1] * a2v[ni][1];
                p1 += acc[mi][ni][2] * a2v[ni][0] + acc[mi][ni][3] * a2v[ni][1];
            }
            p0 += __shfl_xor_sync(0xFFFFFFFFu, p0, 1);
            p0 += __shfl_xor_sync(0xFFFFFFFFu, p0, 2);
            p1 += __shfl_xor_sync(0xFFFFFFFFu, p1, 1);
            p1 += __shfl_xor_sync(0xFFFFFFFFu, p1, 2);
            if (l4 == 0) {
                int r = m0 + wm * 64 + mi * 16 + lg;
                atomicAdd(&g_s2[hh * NROW + r], p0);
                atomicAdd(&g_s2[hh * NROW + r + 8], p1);
            }
        }
    }
}

// ------------------------- prep / small kernels -------------------------
__global__ void k_prep(const float* __restrict__ X, const float* __restrict__ kern) {
    int b = blockIdx.x;
    if (b < 4096) {                                    // X -> fp16
        size_t i = (size_t)b * 256 + threadIdx.x;
        float4 v = reinterpret_cast<const float4*>(X)[i];
        __half2* d = reinterpret_cast<__half2*>(g_X16);
        d[2 * i]     = __floats2half2_rn(v.x, v.y);
        d[2 * i + 1] = __floats2half2_rn(v.z, v.w);
    } else if (b < 5120) {                             // kernels -> Wt[f][c]
        size_t i = (size_t)(b - 4096) * 256 + threadIdx.x;
        int f = (int)(i >> 9), c = (int)(i & 511);
        g_Wt[i] = __float2half_rn(kern[((size_t)(c >> 6) * 512 + f) * 64 + (c & 63)]);
    } else if (b < 5376) {                             // zero s2 (graph-replay safe)
        g_s2[(b - 5120) * 256 + threadIdx.x] = 0.f;
    } else {
        if (threadIdx.x < 8) g_mxi[threadIdx.x] = 0u;
    }
}

__global__ void k_max64() {                            // grid 64, block 256
    __shared__ float sm[256];
    int h = blockIdx.x >> 3, seg = blockIdx.x & 7;
    float m = -1e30f;
    for (int i = seg * 1024 + threadIdx.x; i < (seg + 1) * 1024; i += 256)
        m = fmaxf(m, g_s2[h * NROW + i]);
    sm[threadIdx.x] = m;
    __syncthreads();
    for (int s = 128; s > 0; s >>= 1) {
        if (threadIdx.x < s) sm[threadIdx.x] = fmaxf(sm[threadIdx.x], sm[threadIdx.x + s]);
        __syncthreads();
    }
    if (threadIdx.x == 0) atomicMax(&g_mxi[h], enc_f(sm[0]));
}

__global__ void k_buildB() {                           // grid 8192, block 256
    int n = blockIdx.x;
    int c2 = threadIdx.x;                              // cols 2*c2, 2*c2+1 (same head)
    int h = c2 >> 5;
    float w = __expf(g_s2[h * NROW + n] - dec_f(g_mxi[h]));
    float2 wx = *reinterpret_cast<const float2*>(&g_WX[(size_t)n * FDIM + 2 * c2]);
    *reinterpret_cast<__half2*>(&g_B[(size_t)n * LDBM + 2 * c2]) =
        __floats2half2_rn(w * wx.x, w * wx.y);
    if (c2 < 8) {                                      // den col for head c2
        float wd = __expf(g_s2[c2 * NROW + n] - dec_f(g_mxi[c2]));
        g_B[(size_t)n * LDBM + 512 + c2] = __float2half_rn(wd);
    }
}

// ------------------------- launcher -------------------------
extern "C" void kernel_launch(void* const* d_in, const int* in_sizes, int n_in,
                              void* d_out, int out_size)
{
    const float* X    = (const float*)d_in[0];
    const float* A    = (const float*)d_in[1];
    const float* kern = (const float*)d_in[2];
    const float* attn = (const float*)d_in[3];
    float* out = (float*)d_out;

    void *pX16, *pWt, *pWX, *pB;
    cudaGetSymbolAddress(&pX16, g_X16);
    cudaGetSymbolAddress(&pWt,  g_Wt);
    cudaGetSymbolAddress(&pWX,  g_WX);
    cudaGetSymbolAddress(&pB,   g_B);

    constexpr int SM_WX   = 4 * 10240 + 4 * (32 * 136 * 2);                    // 75776
    constexpr int SM_MAIN = 4 * 16384 + 2 * 10240 + 4 * (32 * 280 * 2) + 4096; // 161792
    cudaFuncSetAttribute(k_mm<FDIM, FDIM, 128, false, false, true>,
                         cudaFuncAttributeMaxDynamicSharedMemorySize, SM_WX);
    cudaFuncSetAttribute(k_mm<NROW, LDBM, 256, true, true, false>,
                         cudaFuncAttributeMaxDynamicSharedMemorySize, SM_MAIN);

    // 1: fp16 operands + zero s2/max
    k_prep<<<5377, 256>>>(X, kern);
    // 2: WX = X16 @ Wt, with fused s2 accumulation
    k_mm<FDIM, FDIM, 128, false, false, true><<<dim3(4, 64), 256, SM_WX>>>(
        pX16, (const __half*)pWt, (float*)pWX, attn);
    // 3-4: per-head max, B build (feats + den cols)
    k_max64<<<64, 256>>>();
    k_buildB<<<NROW, 256>>>();
    // 5: main fused GEMM (smem-staged A conversion overlapped with tensor drain,
    //    den cols, div+relu epilogue) -> out
    k_mm<NROW, LDBM, 256, true, true, false><<<dim3(2, 64), 256, SM_MAIN>>>(
        A, (const __half*)pB, out, nullptr);
}